// round 13
// baseline (speedup 1.0000x reference)
#include <cuda_runtime.h>
#include <cuda_fp16.h>
#include <stdint.h>

#define Bn 4
#define Sn 2048
#define Dn 1024
#define Hn 16
#define HDn 64
#define Mtot (Bn * Sn)          // 8192

// Scratch (static device globals -- allocation-free per harness rules)
__device__ uint32_t g_maskbits[(size_t)Bn * Sn * Sn / 32];   // 1 bit / elt
__device__ int      g_mask_flag;

// fp16 operand buffers (all hi-only)
__device__ __half g_ahi[(size_t)Mtot * Dn];   // X hi, then attn-out hi
__device__ __half g_whi[(size_t)4 * Dn * Dn]; // wq,wk,wv,wo hi
__device__ __half g_qhi[(size_t)Bn * Hn * Sn * HDn];  // [B,H,S,HD]
__device__ __half g_khi[(size_t)Bn * Hn * Sn * HDn];
__device__ __half g_vhi[(size_t)Bn * Hn * Sn * HDn];

// ===========================================================================
// PTX helpers (base ISA: ldmatrix / mma.sync / cp.async)
// ===========================================================================
__device__ __forceinline__ uint32_t smem_u32(const void* p) {
    uint32_t a;
    asm("{ .reg .u64 t; cvta.to.shared.u64 t, %1; cvt.u32.u64 %0, t; }" : "=r"(a) : "l"(p));
    return a;
}

#define LDSM4(r0, r1, r2, r3, addr) \
    asm volatile("ldmatrix.sync.aligned.m8n8.x4.shared.b16 {%0,%1,%2,%3}, [%4];" \
        : "=r"(r0), "=r"(r1), "=r"(r2), "=r"(r3) : "r"(addr))

#define LDSM4T(r0, r1, r2, r3, addr) \
    asm volatile("ldmatrix.sync.aligned.m8n8.x4.trans.shared.b16 {%0,%1,%2,%3}, [%4];" \
        : "=r"(r0), "=r"(r1), "=r"(r2), "=r"(r3) : "r"(addr))

#define MMA16816(c, a0, a1, a2, a3, b0, b1) \
    asm volatile("mma.sync.aligned.m16n8k16.row.col.f32.f16.f16.f32 " \
        "{%0,%1,%2,%3}, {%4,%5,%6,%7}, {%8,%9}, {%0,%1,%2,%3};" \
        : "+f"((c)[0]), "+f"((c)[1]), "+f"((c)[2]), "+f"((c)[3]) \
        : "r"(a0), "r"(a1), "r"(a2), "r"(a3), "r"(b0), "r"(b1))

#define CPA16(dst, src) \
    asm volatile("cp.async.cg.shared.global [%0], [%1], 16;" :: "r"(dst), "l"(src) : "memory")
#define CPA_COMMIT() asm volatile("cp.async.commit_group;" ::: "memory")
#define CPA_WAITG(n) asm volatile("cp.async.wait_group %0;" :: "n"(n) : "memory")

// ===========================================================================
// Mask: dtype sniffer + vectorized bit-packer (4 elems/thread, shuffle-OR)
// ===========================================================================
__global__ void detect_mask_kernel(const uint32_t* __restrict__ m)
{
    __shared__ int cnt_w;
    if (threadIdx.x == 0) cnt_w = 0;
    __syncthreads();
    uint32_t w = m[threadIdx.x];
    if (w == 0u || w == 1u || w == 0x3F800000u) atomicAdd(&cnt_w, 1);
    __syncthreads();
    if (threadIdx.x == 0) g_mask_flag = (cnt_w > 200) ? 1 : 0;  // 1 = 4-byte elems
}

__global__ __launch_bounds__(256) void pack_mask_kernel(const void* __restrict__ m)
{
    const size_t idx = (size_t)blockIdx.x * 256 + threadIdx.x;
    const int lane = threadIdx.x & 31;
    uint32_t nib;
    if (g_mask_flag) {
        uint4 v = ((const uint4*)m)[idx];
        nib = (v.x != 0u) | ((v.y != 0u) << 1) | ((v.z != 0u) << 2) | ((v.w != 0u) << 3);
    } else {
        uint32_t v = ((const uint32_t*)m)[idx];
        nib = ((v & 0x000000FFu) ? 1u : 0u) | ((v & 0x0000FF00u) ? 2u : 0u)
            | ((v & 0x00FF0000u) ? 4u : 0u) | ((v & 0xFF000000u) ? 8u : 0u);
    }
    uint32_t sh = nib << (4 * (lane & 7));
    sh |= __shfl_xor_sync(0xffffffffu, sh, 1);
    sh |= __shfl_xor_sync(0xffffffffu, sh, 2);
    sh |= __shfl_xor_sync(0xffffffffu, sh, 4);
    if ((lane & 7) == 0) g_maskbits[idx >> 3] = sh;
}

// ===========================================================================
// fp32 -> fp16 hi conversion: one launch covers X (8 slices) + 4 weights.
// ===========================================================================
__global__ __launch_bounds__(256) void cvt_all_kernel(
    const float* __restrict__ x,
    const float* __restrict__ w0, const float* __restrict__ w1,
    const float* __restrict__ w2, const float* __restrict__ w3)
{
    const int z = blockIdx.y;
    const float* src;
    __half* dst;
    if (z < 8) {
        src = x   + (size_t)z * (Mtot / 8) * Dn;
        dst = g_ahi + (size_t)z * (Mtot / 8) * Dn;
    } else {
        const float* ws[4] = {w0, w1, w2, w3};
        src = ws[z - 8];
        dst = g_whi + (size_t)(z - 8) * Dn * Dn;
    }
    const size_t i = (size_t)blockIdx.x * 256 + threadIdx.x;
    float4 v = ((const float4*)src)[i];
    __half2 a = __floats2half2_rn(v.x, v.y);
    __half2 b = __floats2half2_rn(v.z, v.w);
    ((uint2*)dst)[i] = make_uint2(*(uint32_t*)&a, *(uint32_t*)&b);
}

// ===========================================================================
// fp16 tensor-core GEMM (single pass): C[128x128] = Ah[.,1024] @ Wh[.,1024]^T
// KC=64 K-chunks, 3-stage cp.async ring, ONE __syncthreads per 64-K chunk.
// ===========================================================================
#define KC 64
#define GP 72                    // halves per smem row (144 B, conflict-free)
#define GPB 144
#define GTILE (128 * GPB)        // 18432 B per operand tile
#define GSTG (2 * GTILE)         // Ah + Bh = 36864
#define GNSTAGE 3
#define DYNSM (GNSTAGE * GSTG)   // 110592

__global__ __launch_bounds__(256, 2) void mma_gemm_kernel(
    const __half* __restrict__ Ahi,
    const __half* __restrict__ Whi,
    float* __restrict__ out,
    int mode)
{
    extern __shared__ char dsm[];
    const uint32_t sbase = smem_u32(dsm);

    const int tid  = threadIdx.x;
    const int lane = tid & 31;
    const int wid  = tid >> 5;
    const int wr   = wid >> 2;
    const int wc   = wid & 3;
    const int bm   = blockIdx.y * 128;
    const int bn   = blockIdx.x * 128;
    const int z    = blockIdx.z;

    const __half* WhiZ = Whi + (size_t)z * Dn * Dn;

    const int row = tid >> 1;
    const int seg = tid & 1;
    const __half* sA_h = Ahi  + (size_t)(bm + row) * Dn + seg * 32;
    const __half* sB_h = WhiZ + (size_t)(bn + row) * Dn + seg * 32;
    const uint32_t sd0 = sbase + (uint32_t)row * GPB + seg * 64;

    const int NC = Dn / KC;     // 16
    auto issue = [&](int ck) {
        const uint32_t sd = sd0 + (ck % GNSTAGE) * GSTG;
        const size_t o = (size_t)ck * KC;
        CPA16(sd,              sA_h + o);
        CPA16(sd + 16,         sA_h + o + 8);
        CPA16(sd + 32,         sA_h + o + 16);
        CPA16(sd + 48,         sA_h + o + 24);
        CPA16(sd + GTILE,      sB_h + o);
        CPA16(sd + GTILE + 16, sB_h + o + 8);
        CPA16(sd + GTILE + 32, sB_h + o + 16);
        CPA16(sd + GTILE + 48, sB_h + o + 24);
        CPA_COMMIT();
    };

    float acc[4][4][4];
    #pragma unroll
    for (int i = 0; i < 4; i++)
        #pragma unroll
        for (int j = 0; j < 4; j++)
            #pragma unroll
            for (int v = 0; v < 4; v++) acc[i][j][v] = 0.f;

    issue(0);
    issue(1);

    for (int ck = 0; ck < NC; ck++) {
        // ensure chunk ck complete (pending: ck, ck+1 except at tail)
        if (ck < NC - 1) { CPA_WAITG(1); } else { CPA_WAITG(0); }
        __syncthreads();
        if (ck + 2 < NC) issue(ck + 2);   // stage (ck+2)%3 freed at ck-1 + sync

        const uint32_t stg = sbase + (ck % GNSTAGE) * GSTG;
        #pragma unroll
        for (int ks = 0; ks < 4; ks++) {
            uint32_t b[4][2];
            #pragma unroll
            for (int jj = 0; jj < 2; jj++) {
                int n = wc * 32 + jj * 16 + ((lane >> 4) & 1) * 8 + (lane & 7);
                int k = ks * 16 + ((lane >> 3) & 1) * 8;
                uint32_t ad = stg + GTILE + (uint32_t)(n * GP + k) * 2;
                LDSM4(b[2 * jj][0], b[2 * jj][1], b[2 * jj + 1][0], b[2 * jj + 1][1], ad);
            }
            #pragma unroll
            for (int i = 0; i < 4; i++) {
                int m = wr * 64 + i * 16 + ((lane >> 3) & 1) * 8 + (lane & 7);
                int k = ks * 16 + ((lane >> 4) & 1) * 8;
                uint32_t adh = stg + (uint32_t)(m * GP + k) * 2;
                uint32_t a0, a1, a2, a3;
                LDSM4(a0, a1, a2, a3, adh);
                #pragma unroll
                for (int j = 0; j < 4; j++)
                    MMA16816(acc[i][j], a0, a1, a2, a3, b[j][0], b[j][1]);
            }
        }
    }

    // ---- epilogue ----
    #pragma unroll
    for (int i = 0; i < 4; i++) {
        #pragma unroll
        for (int j = 0; j < 4; j++) {
            int ml = wr * 64 + i * 16 + (lane >> 2);
            int nl = wc * 32 + j * 8 + 2 * (lane & 3);
            int m = bm + ml, n = bn + nl;
            if (mode == 0) {
                __half* dh = (z == 0) ? g_qhi : (z == 1) ? g_khi : g_vhi;
                int bb2 = m >> 11, ss = m & 2047;
                int hh = n >> 6,  hd = n & 63;
                size_t base = (((size_t)bb2 * Hn + hh) * Sn + ss) * HDn + hd;
                __half2 h = __floats2half2_rn(acc[i][j][0], acc[i][j][1]);
                *(uint32_t*)&dh[base] = *(uint32_t*)&h;
                h = __floats2half2_rn(acc[i][j][2], acc[i][j][3]);
                *(uint32_t*)&dh[base + 8 * HDn] = *(uint32_t*)&h;
            } else {
                *(float2*)&out[(size_t)m * Dn + n] =
                    make_float2(acc[i][j][0], acc[i][j][1]);
                *(float2*)&out[(size_t)(m + 8) * Dn + n] =
                    make_float2(acc[i][j][2], acc[i][j][3]);
            }
        }
    }
}

// ===========================================================================
// Tensor-core flash attention, single-pass fp16 MMAs (Qh*Kh, Ph*Vh).
// 2-stage cp.async, ONE __syncthreads per K-tile (wait -> sync -> issue).
// ===========================================================================
#define AP     72                 // halves per row (144 B)
#define APB    144
#define TILE18 18432              // 128 * 144
#define OFF_KH 0
#define OFF_VH 18432
#define OFF_MK 36864              // 128 rows x 16 B of bits
#define KVBUF  38912              // 2*18432 + 2048
#define QSZ    18432
#define ATT_SMEM (QSZ + 2 * KVBUF)   // 96256

__global__ __launch_bounds__(256, 2) void attn_mma_kernel()
{
    extern __shared__ char smn[];
    const uint32_t sb = smem_u32(smn);
    const int tid = threadIdx.x, lane = tid & 31, w = tid >> 5;
    const int qt = blockIdx.x, bh = blockIdx.y;
    const int b = bh >> 4, h = bh & 15;
    const int qbase = qt * 128;
    const size_t head = (size_t)bh * Sn * HDn;
    const int row = tid >> 1, seg = tid & 1;
    const uint32_t rowb = (uint32_t)row * APB + seg * 64;

    // Q tile (persistent)
    {
        const uint4* qh = (const uint4*)(g_qhi + head + (size_t)(qbase + row) * HDn + seg * 32);
        uint4* dh = (uint4*)(smn + rowb);
        #pragma unroll
        for (int i = 0; i < 4; i++) dh[i] = qh[i];
    }

    const char* mbits_row = (const char*)g_maskbits + ((size_t)b * Sn + qbase + row) * (Sn / 8);
    const char* gkh = (const char*)(g_khi + head + (size_t)row * HDn + seg * 32);
    const char* gvh = (const char*)(g_vhi + head + (size_t)row * HDn + seg * 32);

    auto issue_tile = [&](int kt, int s) {
        const uint32_t bb = sb + QSZ + s * KVBUF;
        const size_t go = (size_t)kt * 128 * HDn * 2;
        #pragma unroll
        for (int i = 0; i < 4; i++) {
            CPA16(bb + OFF_KH + rowb + i * 16, gkh + go + i * 16);
            CPA16(bb + OFF_VH + rowb + i * 16, gvh + go + i * 16);
        }
        if (seg == 0)
            CPA16(bb + OFF_MK + (uint32_t)row * 16, mbits_row + kt * 16);
        CPA_COMMIT();
    };

    float o[8][4];
    #pragma unroll
    for (int j = 0; j < 8; j++)
        #pragma unroll
        for (int v = 0; v < 4; v++) o[j][v] = 0.f;
    float m_r0 = -1e30f, m_r1 = -1e30f, l_r0 = 0.f, l_r1 = 0.f;

    const int wq0  = w * 16;
    const int r_lo = lane >> 2, c4 = lane & 3;
    const int mA = wq0 + ((lane >> 3) & 1) * 8 + (lane & 7);
    const int kA = ((lane >> 4) & 1) * 8;
    const uint32_t aQh = sb + (uint32_t)(mA * AP + kA) * 2;
    const int nK = ((lane >> 4) & 1) * 8 + (lane & 7);
    const int kK = ((lane >> 3) & 1) * 8;
    const int kV = ((lane >> 3) & 1) * 8 + (lane & 7);
    const int nV = ((lane >> 4) & 1) * 8;

    issue_tile(0, 0);

    for (int kt = 0; kt < 16; kt++) {
        const int s = kt & 1;
        CPA_WAITG(0);            // tile kt complete (only one in flight)
        __syncthreads();         // all warps done with buffer s (prev use)
        if (kt < 15) issue_tile(kt + 1, s ^ 1);   // overlaps compute below
        const uint32_t bb = sb + QSZ + s * KVBUF;

        // ---- S = Qh Kh^T (single pass) ----
        float sacc[16][4];
        #pragma unroll
        for (int j = 0; j < 16; j++)
            #pragma unroll
            for (int v = 0; v < 4; v++) sacc[j][v] = 0.f;

        #pragma unroll
        for (int ks = 0; ks < 4; ks++) {
            uint32_t ah0, ah1, ah2, ah3;
            LDSM4(ah0, ah1, ah2, ah3, aQh + ks * 32);
            #pragma unroll
            for (int jj = 0; jj < 8; jj++) {
                const int j0 = 2 * jj;
                const uint32_t kaddr =
                    bb + OFF_KH + (uint32_t)((j0 * 8 + nK) * AP + ks * 16 + kK) * 2;
                uint32_t b0, b1, b2, b3;
                LDSM4(b0, b1, b2, b3, kaddr);
                MMA16816(sacc[j0],     ah0, ah1, ah2, ah3, b0, b1);
                MMA16816(sacc[j0 + 1], ah0, ah1, ah2, ah3, b2, b3);
            }
        }

        // ---- bit-mask + online softmax ----
        const uint4 mw0 = *(const uint4*)(smn + QSZ + s * KVBUF + OFF_MK + (wq0 + r_lo) * 16);
        const uint4 mw1 = *(const uint4*)(smn + QSZ + s * KVBUF + OFF_MK + (wq0 + r_lo + 8) * 16);
        uint32_t w0a[4] = {mw0.x, mw0.y, mw0.z, mw0.w};
        uint32_t w1a[4] = {mw1.x, mw1.y, mw1.z, mw1.w};
        float tm0 = -1e30f, tm1 = -1e30f;
        #pragma unroll
        for (int j = 0; j < 16; j++) {
            const uint32_t bits0 = w0a[j >> 2] >> (8 * (j & 3) + 2 * c4);
            const uint32_t bits1 = w1a[j >> 2] >> (8 * (j & 3) + 2 * c4);
            float s0 = (bits0 & 1u) ? sacc[j][0] * 0.125f : -1e30f;
            float s1 = (bits0 & 2u) ? sacc[j][1] * 0.125f : -1e30f;
            float s2 = (bits1 & 1u) ? sacc[j][2] * 0.125f : -1e30f;
            float s3 = (bits1 & 2u) ? sacc[j][3] * 0.125f : -1e30f;
            sacc[j][0] = s0; sacc[j][1] = s1; sacc[j][2] = s2; sacc[j][3] = s3;
            tm0 = fmaxf(tm0, fmaxf(s0, s1));
            tm1 = fmaxf(tm1, fmaxf(s2, s3));
        }
        tm0 = fmaxf(tm0, __shfl_xor_sync(0xffffffffu, tm0, 1));
        tm0 = fmaxf(tm0, __shfl_xor_sync(0xffffffffu, tm0, 2));
        tm1 = fmaxf(tm1, __shfl_xor_sync(0xffffffffu, tm1, 1));
        tm1 = fmaxf(tm1, __shfl_xor_sync(0xffffffffu, tm1, 2));
        const float mn0 = fmaxf(m_r0, tm0), mn1 = fmaxf(m_r1, tm1);
        const float al_0 = __expf(m_r0 - mn0), al_1 = __expf(m_r1 - mn1);
        m_r0 = mn0; m_r1 = mn1;
        float ps0 = 0.f, ps1 = 0.f;
        #pragma unroll
        for (int j = 0; j < 16; j++) {
            float p0 = __expf(sacc[j][0] - mn0); sacc[j][0] = p0; ps0 += p0;
            float p1 = __expf(sacc[j][1] - mn0); sacc[j][1] = p1; ps0 += p1;
            float p2 = __expf(sacc[j][2] - mn1); sacc[j][2] = p2; ps1 += p2;
            float p3 = __expf(sacc[j][3] - mn1); sacc[j][3] = p3; ps1 += p3;
        }
        ps0 += __shfl_xor_sync(0xffffffffu, ps0, 1);
        ps0 += __shfl_xor_sync(0xffffffffu, ps0, 2);
        ps1 += __shfl_xor_sync(0xffffffffu, ps1, 1);
        ps1 += __shfl_xor_sync(0xffffffffu, ps1, 2);
        l_r0 = l_r0 * al_0 + ps0;
        l_r1 = l_r1 * al_1 + ps1;
        #pragma unroll
        for (int j = 0; j < 8; j++) {
            o[j][0] *= al_0; o[j][1] *= al_0; o[j][2] *= al_1; o[j][3] *= al_1;
        }

        // ---- O += Ph Vh (single pass, V via ldmatrix.trans) ----
        #pragma unroll
        for (int kt2 = 0; kt2 < 8; kt2++) {
            const int j0 = 2 * kt2;
            __half2 hp;
            hp = __floats2half2_rn(sacc[j0][0], sacc[j0][1]);
            const uint32_t p0 = *(uint32_t*)&hp;
            hp = __floats2half2_rn(sacc[j0][2], sacc[j0][3]);
            const uint32_t p1 = *(uint32_t*)&hp;
            hp = __floats2half2_rn(sacc[j0 + 1][0], sacc[j0 + 1][1]);
            const uint32_t p2 = *(uint32_t*)&hp;
            hp = __floats2half2_rn(sacc[j0 + 1][2], sacc[j0 + 1][3]);
            const uint32_t p3 = *(uint32_t*)&hp;
            #pragma unroll
            for (int jj = 0; jj < 4; jj++) {
                const int jv = 2 * jj;
                const uint32_t va =
                    bb + OFF_VH + (uint32_t)((kt2 * 16 + kV) * AP + jv * 8 + nV) * 2;
                uint32_t v0, v1, v2, v3;
                LDSM4T(v0, v1, v2, v3, va);
                MMA16816(o[jv],     p0, p1, p2, p3, v0, v1);
                MMA16816(o[jv + 1], p0, p1, p2, p3, v2, v3);
            }
        }
    }

    // ---- epilogue: O/l -> fp16 into out-GEMM operand buffer ----
    const float inv0 = 1.f / fmaxf(l_r0, 1e-30f);
    const float inv1 = 1.f / fmaxf(l_r1, 1e-30f);
    const int r1g = qbase + wq0 + r_lo;
    #pragma unroll
    for (int j = 0; j < 8; j++) {
        const size_t idx0 = ((size_t)b * Sn + r1g) * Dn + h * 64 + j * 8 + 2 * c4;
        __half2 h2;
        h2 = __floats2half2_rn(o[j][0] * inv0, o[j][1] * inv0);
        *(uint32_t*)&g_ahi[idx0] = *(uint32_t*)&h2;
        h2 = __floats2half2_rn(o[j][2] * inv1, o[j][3] * inv1);
        *(uint32_t*)&g_ahi[idx0 + 8 * Dn] = *(uint32_t*)&h2;
    }
}

// ---------------------------------------------------------------------------
extern "C" void kernel_launch(void* const* d_in, const int* in_sizes, int n_in,
                              void* d_out, int out_size)
{
    const float* x    = (const float*)d_in[0];
    const void*  mask = d_in[1];
    const float* wq   = (const float*)d_in[2];
    const float* wk   = (const float*)d_in[3];
    const float* wv   = (const float*)d_in[4];
    const float* wo   = (const float*)d_in[5];
    float* out = (float*)d_out;

    cudaFuncSetAttribute(mma_gemm_kernel,
                         cudaFuncAttributeMaxDynamicSharedMemorySize, DYNSM);
    cudaFuncSetAttribute(attn_mma_kernel,
                         cudaFuncAttributeMaxDynamicSharedMemorySize, ATT_SMEM);

    detect_mask_kernel<<<1, 256>>>((const uint32_t*)mask);
    const size_t mask_elts = (size_t)Bn * Sn * Sn;
    pack_mask_kernel<<<(unsigned)(mask_elts / 1024), 256>>>(mask);

    __half *ahi, *whi;
    cudaGetSymbolAddress((void**)&ahi, g_ahi);
    cudaGetSymbolAddress((void**)&whi, g_whi);

    // X (8 slices) + 4 weights -> fp16 in one launch
    cvt_all_kernel<<<dim3((unsigned)((size_t)Dn * Dn / 1024), 12), 256>>>(x, wq, wk, wv, wo);

    // QKV projections -> fp16 Q/K/V, single-pass
    dim3 g1(Dn / 128, Mtot / 128, 3);
    mma_gemm_kernel<<<g1, 256, DYNSM>>>(ahi, whi, nullptr, 0);

    // Tensor-core flash attention -> writes g_ahi
    dim3 g2(Sn / 128, Bn * Hn);
    attn_mma_kernel<<<g2, 256, ATT_SMEM>>>();

    // Output projection (single-pass)
    dim3 g3(Dn / 128, Mtot / 128, 1);
    mma_gemm_kernel<<<g3, 256, DYNSM>>>(ahi, whi + 3 * (size_t)Dn * Dn, out, 1);
}

// round 14
// speedup vs baseline: 1.0579x; 1.0579x over previous
#include <cuda_runtime.h>
#include <cuda_fp16.h>
#include <stdint.h>

#define Bn 4
#define Sn 2048
#define Dn 1024
#define Hn 16
#define HDn 64
#define Mtot (Bn * Sn)          // 8192
#define NITEMS (16 * 64)        // qt x (b*h) work items for attention

// Scratch (static device globals -- allocation-free per harness rules)
__device__ uint32_t g_maskbits[(size_t)Bn * Sn * Sn / 32];   // 1 bit / elt
__device__ int      g_mask_flag;
__device__ int      g_work;                                  // attention work counter

// fp16 operand buffers (all hi-only)
__device__ __half g_ahi[(size_t)Mtot * Dn];   // X hi, then attn-out hi
__device__ __half g_whi[(size_t)4 * Dn * Dn]; // wq,wk,wv,wo hi
__device__ __half g_qhi[(size_t)Bn * Hn * Sn * HDn];  // [B,H,S,HD]
__device__ __half g_khi[(size_t)Bn * Hn * Sn * HDn];
__device__ __half g_vhi[(size_t)Bn * Hn * Sn * HDn];

// ===========================================================================
// PTX helpers (base ISA: ldmatrix / mma.sync / cp.async)
// ===========================================================================
__device__ __forceinline__ uint32_t smem_u32(const void* p) {
    uint32_t a;
    asm("{ .reg .u64 t; cvta.to.shared.u64 t, %1; cvt.u32.u64 %0, t; }" : "=r"(a) : "l"(p));
    return a;
}

#define LDSM4(r0, r1, r2, r3, addr) \
    asm volatile("ldmatrix.sync.aligned.m8n8.x4.shared.b16 {%0,%1,%2,%3}, [%4];" \
        : "=r"(r0), "=r"(r1), "=r"(r2), "=r"(r3) : "r"(addr))

#define LDSM4T(r0, r1, r2, r3, addr) \
    asm volatile("ldmatrix.sync.aligned.m8n8.x4.trans.shared.b16 {%0,%1,%2,%3}, [%4];" \
        : "=r"(r0), "=r"(r1), "=r"(r2), "=r"(r3) : "r"(addr))

#define MMA16816(c, a0, a1, a2, a3, b0, b1) \
    asm volatile("mma.sync.aligned.m16n8k16.row.col.f32.f16.f16.f32 " \
        "{%0,%1,%2,%3}, {%4,%5,%6,%7}, {%8,%9}, {%0,%1,%2,%3};" \
        : "+f"((c)[0]), "+f"((c)[1]), "+f"((c)[2]), "+f"((c)[3]) \
        : "r"(a0), "r"(a1), "r"(a2), "r"(a3), "r"(b0), "r"(b1))

#define CPA16(dst, src) \
    asm volatile("cp.async.cg.shared.global [%0], [%1], 16;" :: "r"(dst), "l"(src) : "memory")
#define CPA_COMMIT() asm volatile("cp.async.commit_group;" ::: "memory")
#define CPA_WAITG(n) asm volatile("cp.async.wait_group %0;" :: "n"(n) : "memory")

// ===========================================================================
// Mask: dtype sniffer (also resets work counter) + vectorized bit-packer
// ===========================================================================
__global__ void detect_mask_kernel(const uint32_t* __restrict__ m)
{
    __shared__ int cnt_w;
    if (threadIdx.x == 0) { cnt_w = 0; g_work = 0; }
    __syncthreads();
    uint32_t w = m[threadIdx.x];
    if (w == 0u || w == 1u || w == 0x3F800000u) atomicAdd(&cnt_w, 1);
    __syncthreads();
    if (threadIdx.x == 0) g_mask_flag = (cnt_w > 200) ? 1 : 0;  // 1 = 4-byte elems
}

__global__ __launch_bounds__(256) void pack_mask_kernel(const void* __restrict__ m)
{
    const size_t idx = (size_t)blockIdx.x * 256 + threadIdx.x;
    const int lane = threadIdx.x & 31;
    uint32_t nib;
    if (g_mask_flag) {
        uint4 v = ((const uint4*)m)[idx];
        nib = (v.x != 0u) | ((v.y != 0u) << 1) | ((v.z != 0u) << 2) | ((v.w != 0u) << 3);
    } else {
        uint32_t v = ((const uint32_t*)m)[idx];
        nib = ((v & 0x000000FFu) ? 1u : 0u) | ((v & 0x0000FF00u) ? 2u : 0u)
            | ((v & 0x00FF0000u) ? 4u : 0u) | ((v & 0xFF000000u) ? 8u : 0u);
    }
    uint32_t sh = nib << (4 * (lane & 7));
    sh |= __shfl_xor_sync(0xffffffffu, sh, 1);
    sh |= __shfl_xor_sync(0xffffffffu, sh, 2);
    sh |= __shfl_xor_sync(0xffffffffu, sh, 4);
    if ((lane & 7) == 0) g_maskbits[idx >> 3] = sh;
}

// ===========================================================================
// fp32 -> fp16 hi conversion: one launch covers X (8 slices) + 4 weights.
// ===========================================================================
__global__ __launch_bounds__(256) void cvt_all_kernel(
    const float* __restrict__ x,
    const float* __restrict__ w0, const float* __restrict__ w1,
    const float* __restrict__ w2, const float* __restrict__ w3)
{
    const int z = blockIdx.y;
    const float* src;
    __half* dst;
    if (z < 8) {
        src = x   + (size_t)z * (Mtot / 8) * Dn;
        dst = g_ahi + (size_t)z * (Mtot / 8) * Dn;
    } else {
        const float* ws[4] = {w0, w1, w2, w3};
        src = ws[z - 8];
        dst = g_whi + (size_t)(z - 8) * Dn * Dn;
    }
    const size_t i = (size_t)blockIdx.x * 256 + threadIdx.x;
    float4 v = ((const float4*)src)[i];
    __half2 a = __floats2half2_rn(v.x, v.y);
    __half2 b = __floats2half2_rn(v.z, v.w);
    ((uint2*)dst)[i] = make_uint2(*(uint32_t*)&a, *(uint32_t*)&b);
}

// ===========================================================================
// fp16 tensor-core GEMM (R12-proven config): C[128x128] = Ah @ Wh^T
// KC=32, 4-stage cp.async ring, ONE __syncthreads per K-chunk.
// ===========================================================================
#define KC 32
#define PITCH 40                 // halves per smem row (80 B)
#define TILE_B (128 * PITCH * 2) // 10240
#define STG (2 * TILE_B)         // Ah, Bh = 20480
#define NSTAGE 4
#define DYNSM (NSTAGE * STG)     // 81920

__global__ __launch_bounds__(256, 2) void mma_gemm_kernel(
    const __half* __restrict__ Ahi,
    const __half* __restrict__ Whi,
    float* __restrict__ out,
    int mode)
{
    extern __shared__ char dsm[];
    const uint32_t sbase = smem_u32(dsm);

    const int tid  = threadIdx.x;
    const int lane = tid & 31;
    const int wid  = tid >> 5;
    const int wr   = wid >> 2;
    const int wc   = wid & 3;
    const int bm   = blockIdx.y * 128;
    const int bn   = blockIdx.x * 128;
    const int z    = blockIdx.z;

    const __half* WhiZ = Whi + (size_t)z * Dn * Dn;

    const int row = tid >> 1;
    const int gh  = tid & 1;
    const __half* sA_h = Ahi  + (size_t)(bm + row) * Dn + gh * 16;
    const __half* sB_h = WhiZ + (size_t)(bn + row) * Dn + gh * 16;
    const uint32_t sd0 = sbase + (uint32_t)row * (PITCH * 2) + gh * 32;

    const int NC = Dn / KC;     // 32
    auto issue = [&](int ck) {
        const uint32_t sd = sd0 + (ck & (NSTAGE - 1)) * STG;
        const size_t o = (size_t)ck * KC;
        CPA16(sd,                 sA_h + o);
        CPA16(sd + 16,            sA_h + o + 8);
        CPA16(sd + TILE_B,        sB_h + o);
        CPA16(sd + TILE_B + 16,   sB_h + o + 8);
        CPA_COMMIT();
    };

    float acc[4][4][4];
    #pragma unroll
    for (int i = 0; i < 4; i++)
        #pragma unroll
        for (int j = 0; j < 4; j++)
            #pragma unroll
            for (int v = 0; v < 4; v++) acc[i][j][v] = 0.f;

    issue(0);
    issue(1);
    issue(2);

    for (int ck = 0; ck < NC; ck++) {
        if (ck <= NC - 3)      { CPA_WAITG(2); }
        else if (ck == NC - 2) { CPA_WAITG(1); }
        else                   { CPA_WAITG(0); }
        __syncthreads();
        if (ck + 3 < NC) issue(ck + 3);

        const uint32_t stg = sbase + (ck & (NSTAGE - 1)) * STG;
        #pragma unroll
        for (int ks = 0; ks < 2; ks++) {
            uint32_t b[4][2];
            #pragma unroll
            for (int jj = 0; jj < 2; jj++) {
                int n = wc * 32 + jj * 16 + ((lane >> 4) & 1) * 8 + (lane & 7);
                int k = ks * 16 + ((lane >> 3) & 1) * 8;
                uint32_t ad = stg + TILE_B + (uint32_t)(n * PITCH + k) * 2;
                LDSM4(b[2 * jj][0], b[2 * jj][1], b[2 * jj + 1][0], b[2 * jj + 1][1], ad);
            }
            #pragma unroll
            for (int i = 0; i < 4; i++) {
                int m = wr * 64 + i * 16 + ((lane >> 3) & 1) * 8 + (lane & 7);
                int k = ks * 16 + ((lane >> 4) & 1) * 8;
                uint32_t adh = stg + (uint32_t)(m * PITCH + k) * 2;
                uint32_t a0, a1, a2, a3;
                LDSM4(a0, a1, a2, a3, adh);
                #pragma unroll
                for (int j = 0; j < 4; j++)
                    MMA16816(acc[i][j], a0, a1, a2, a3, b[j][0], b[j][1]);
            }
        }
    }

    // ---- epilogue ----
    #pragma unroll
    for (int i = 0; i < 4; i++) {
        #pragma unroll
        for (int j = 0; j < 4; j++) {
            int ml = wr * 64 + i * 16 + (lane >> 2);
            int nl = wc * 32 + j * 8 + 2 * (lane & 3);
            int m = bm + ml, n = bn + nl;
            if (mode == 0) {
                __half* dh = (z == 0) ? g_qhi : (z == 1) ? g_khi : g_vhi;
                int bb2 = m >> 11, ss = m & 2047;
                int hh = n >> 6,  hd = n & 63;
                size_t base = (((size_t)bb2 * Hn + hh) * Sn + ss) * HDn + hd;
                __half2 h = __floats2half2_rn(acc[i][j][0], acc[i][j][1]);
                *(uint32_t*)&dh[base] = *(uint32_t*)&h;
                h = __floats2half2_rn(acc[i][j][2], acc[i][j][3]);
                *(uint32_t*)&dh[base + 8 * HDn] = *(uint32_t*)&h;
            } else {
                *(float2*)&out[(size_t)m * Dn + n] =
                    make_float2(acc[i][j][0], acc[i][j][1]);
                *(float2*)&out[(size_t)(m + 8) * Dn + n] =
                    make_float2(acc[i][j][2], acc[i][j][3]);
            }
        }
    }
}

// ===========================================================================
// Tensor-core flash attention, dynamic-persistent CTAs.
// Each CTA grabs (bh, qt) items from g_work until NITEMS exhausted.
// ===========================================================================
#define AP     72                 // halves per row (144 B)
#define APB    144
#define TILE18 18432              // 128 * 144
#define OFF_KH 0
#define OFF_VH 18432
#define OFF_MK 36864              // 128 rows x 16 B of bits
#define KVBUF  38912              // 2*18432 + 2048
#define QSZ    18432
#define ATT_SMEM (QSZ + 2 * KVBUF)   // 96256

__global__ __launch_bounds__(256, 2) void attn_mma_kernel()
{
    extern __shared__ char smn[];
    const uint32_t sb = smem_u32(smn);
    __shared__ int s_item;
    const int tid = threadIdx.x, lane = tid & 31, w = tid >> 5;
    const int row = tid >> 1, seg = tid & 1;
    const uint32_t rowb = (uint32_t)row * APB + seg * 64;

    const int wq0  = w * 16;
    const int r_lo = lane >> 2, c4 = lane & 3;
    const int mA = wq0 + ((lane >> 3) & 1) * 8 + (lane & 7);
    const int kA = ((lane >> 4) & 1) * 8;
    const uint32_t aQh = sb + (uint32_t)(mA * AP + kA) * 2;
    const int nK = ((lane >> 4) & 1) * 8 + (lane & 7);
    const int kK = ((lane >> 3) & 1) * 8;
    const int kV = ((lane >> 3) & 1) * 8 + (lane & 7);
    const int nV = ((lane >> 4) & 1) * 8;

    for (;;) {
        __syncthreads();                     // drain prior item's smem use
        if (tid == 0) s_item = atomicAdd(&g_work, 1);
        __syncthreads();
        const int item = s_item;
        if (item >= NITEMS) break;

        const int bh = item >> 4;            // consecutive grabs share head -> L2
        const int qt = item & 15;
        const int b = bh >> 4, h = bh & 15;
        const int qbase = qt * 128;
        const size_t head = (size_t)bh * Sn * HDn;

        // Q tile load (plain global reads)
        {
            const uint4* qh = (const uint4*)(g_qhi + head + (size_t)(qbase + row) * HDn + seg * 32);
            uint4* dh = (uint4*)(smn + rowb);
            #pragma unroll
            for (int i = 0; i < 4; i++) dh[i] = qh[i];
        }

        const char* mbits_row = (const char*)g_maskbits + ((size_t)b * Sn + qbase + row) * (Sn / 8);
        const char* gkh = (const char*)(g_khi + head + (size_t)row * HDn + seg * 32);
        const char* gvh = (const char*)(g_vhi + head + (size_t)row * HDn + seg * 32);

        auto issue_tile = [&](int kt, int s) {
            const uint32_t bb = sb + QSZ + s * KVBUF;
            const size_t go = (size_t)kt * 128 * HDn * 2;
            #pragma unroll
            for (int i = 0; i < 4; i++) {
                CPA16(bb + OFF_KH + rowb + i * 16, gkh + go + i * 16);
                CPA16(bb + OFF_VH + rowb + i * 16, gvh + go + i * 16);
            }
            if (seg == 0)
                CPA16(bb + OFF_MK + (uint32_t)row * 16, mbits_row + kt * 16);
            CPA_COMMIT();
        };

        float o[8][4];
        #pragma unroll
        for (int j = 0; j < 8; j++)
            #pragma unroll
            for (int v = 0; v < 4; v++) o[j][v] = 0.f;
        float m_r0 = -1e30f, m_r1 = -1e30f, l_r0 = 0.f, l_r1 = 0.f;

        issue_tile(0, 0);

        for (int kt = 0; kt < 16; kt++) {
            const int s = kt & 1;
            CPA_WAITG(0);
            __syncthreads();
            if (kt < 15) issue_tile(kt + 1, s ^ 1);
            const uint32_t bb = sb + QSZ + s * KVBUF;

            // ---- S = Qh Kh^T ----
            float sacc[16][4];
            #pragma unroll
            for (int j = 0; j < 16; j++)
                #pragma unroll
                for (int v = 0; v < 4; v++) sacc[j][v] = 0.f;

            #pragma unroll
            for (int ks = 0; ks < 4; ks++) {
                uint32_t ah0, ah1, ah2, ah3;
                LDSM4(ah0, ah1, ah2, ah3, aQh + ks * 32);
                #pragma unroll
                for (int jj = 0; jj < 8; jj++) {
                    const int j0 = 2 * jj;
                    const uint32_t kaddr =
                        bb + OFF_KH + (uint32_t)((j0 * 8 + nK) * AP + ks * 16 + kK) * 2;
                    uint32_t b0, b1, b2, b3;
                    LDSM4(b0, b1, b2, b3, kaddr);
                    MMA16816(sacc[j0],     ah0, ah1, ah2, ah3, b0, b1);
                    MMA16816(sacc[j0 + 1], ah0, ah1, ah2, ah3, b2, b3);
                }
            }

            // ---- bit-mask + online softmax ----
            const uint4 mw0 = *(const uint4*)(smn + QSZ + s * KVBUF + OFF_MK + (wq0 + r_lo) * 16);
            const uint4 mw1 = *(const uint4*)(smn + QSZ + s * KVBUF + OFF_MK + (wq0 + r_lo + 8) * 16);
            uint32_t w0a[4] = {mw0.x, mw0.y, mw0.z, mw0.w};
            uint32_t w1a[4] = {mw1.x, mw1.y, mw1.z, mw1.w};
            float tm0 = -1e30f, tm1 = -1e30f;
            #pragma unroll
            for (int j = 0; j < 16; j++) {
                const uint32_t bits0 = w0a[j >> 2] >> (8 * (j & 3) + 2 * c4);
                const uint32_t bits1 = w1a[j >> 2] >> (8 * (j & 3) + 2 * c4);
                float s0 = (bits0 & 1u) ? sacc[j][0] * 0.125f : -1e30f;
                float s1 = (bits0 & 2u) ? sacc[j][1] * 0.125f : -1e30f;
                float s2 = (bits1 & 1u) ? sacc[j][2] * 0.125f : -1e30f;
                float s3 = (bits1 & 2u) ? sacc[j][3] * 0.125f : -1e30f;
                sacc[j][0] = s0; sacc[j][1] = s1; sacc[j][2] = s2; sacc[j][3] = s3;
                tm0 = fmaxf(tm0, fmaxf(s0, s1));
                tm1 = fmaxf(tm1, fmaxf(s2, s3));
            }
            tm0 = fmaxf(tm0, __shfl_xor_sync(0xffffffffu, tm0, 1));
            tm0 = fmaxf(tm0, __shfl_xor_sync(0xffffffffu, tm0, 2));
            tm1 = fmaxf(tm1, __shfl_xor_sync(0xffffffffu, tm1, 1));
            tm1 = fmaxf(tm1, __shfl_xor_sync(0xffffffffu, tm1, 2));
            const float mn0 = fmaxf(m_r0, tm0), mn1 = fmaxf(m_r1, tm1);
            const float al_0 = __expf(m_r0 - mn0), al_1 = __expf(m_r1 - mn1);
            m_r0 = mn0; m_r1 = mn1;
            float ps0 = 0.f, ps1 = 0.f;
            #pragma unroll
            for (int j = 0; j < 16; j++) {
                float p0 = __expf(sacc[j][0] - mn0); sacc[j][0] = p0; ps0 += p0;
                float p1 = __expf(sacc[j][1] - mn0); sacc[j][1] = p1; ps0 += p1;
                float p2 = __expf(sacc[j][2] - mn1); sacc[j][2] = p2; ps1 += p2;
                float p3 = __expf(sacc[j][3] - mn1); sacc[j][3] = p3; ps1 += p3;
            }
            ps0 += __shfl_xor_sync(0xffffffffu, ps0, 1);
            ps0 += __shfl_xor_sync(0xffffffffu, ps0, 2);
            ps1 += __shfl_xor_sync(0xffffffffu, ps1, 1);
            ps1 += __shfl_xor_sync(0xffffffffu, ps1, 2);
            l_r0 = l_r0 * al_0 + ps0;
            l_r1 = l_r1 * al_1 + ps1;
            #pragma unroll
            for (int j = 0; j < 8; j++) {
                o[j][0] *= al_0; o[j][1] *= al_0; o[j][2] *= al_1; o[j][3] *= al_1;
            }

            // ---- O += Ph Vh (V via ldmatrix.trans) ----
            #pragma unroll
            for (int kt2 = 0; kt2 < 8; kt2++) {
                const int j0 = 2 * kt2;
                __half2 hp;
                hp = __floats2half2_rn(sacc[j0][0], sacc[j0][1]);
                const uint32_t p0 = *(uint32_t*)&hp;
                hp = __floats2half2_rn(sacc[j0][2], sacc[j0][3]);
                const uint32_t p1 = *(uint32_t*)&hp;
                hp = __floats2half2_rn(sacc[j0 + 1][0], sacc[j0 + 1][1]);
                const uint32_t p2 = *(uint32_t*)&hp;
                hp = __floats2half2_rn(sacc[j0 + 1][2], sacc[j0 + 1][3]);
                const uint32_t p3 = *(uint32_t*)&hp;
                #pragma unroll
                for (int jj = 0; jj < 4; jj++) {
                    const int jv = 2 * jj;
                    const uint32_t va =
                        bb + OFF_VH + (uint32_t)((kt2 * 16 + kV) * AP + jv * 8 + nV) * 2;
                    uint32_t v0, v1, v2, v3;
                    LDSM4T(v0, v1, v2, v3, va);
                    MMA16816(o[jv],     p0, p1, p2, p3, v0, v1);
                    MMA16816(o[jv + 1], p0, p1, p2, p3, v2, v3);
                }
            }
        }

        // ---- epilogue: O/l -> fp16 into out-GEMM operand buffer ----
        const float inv0 = 1.f / fmaxf(l_r0, 1e-30f);
        const float inv1 = 1.f / fmaxf(l_r1, 1e-30f);
        const int r1g = qbase + wq0 + r_lo;
        #pragma unroll
        for (int j = 0; j < 8; j++) {
            const size_t idx0 = ((size_t)b * Sn + r1g) * Dn + h * 64 + j * 8 + 2 * c4;
            __half2 h2;
            h2 = __floats2half2_rn(o[j][0] * inv0, o[j][1] * inv0);
            *(uint32_t*)&g_ahi[idx0] = *(uint32_t*)&h2;
            h2 = __floats2half2_rn(o[j][2] * inv1, o[j][3] * inv1);
            *(uint32_t*)&g_ahi[idx0 + 8 * Dn] = *(uint32_t*)&h2;
        }
    }
}

// ---------------------------------------------------------------------------
extern "C" void kernel_launch(void* const* d_in, const int* in_sizes, int n_in,
                              void* d_out, int out_size)
{
    const float* x    = (const float*)d_in[0];
    const void*  mask = d_in[1];
    const float* wq   = (const float*)d_in[2];
    const float* wk   = (const float*)d_in[3];
    const float* wv   = (const float*)d_in[4];
    const float* wo   = (const float*)d_in[5];
    float* out = (float*)d_out;

    cudaFuncSetAttribute(mma_gemm_kernel,
                         cudaFuncAttributeMaxDynamicSharedMemorySize, DYNSM);
    cudaFuncSetAttribute(attn_mma_kernel,
                         cudaFuncAttributeMaxDynamicSharedMemorySize, ATT_SMEM);

    detect_mask_kernel<<<1, 256>>>((const uint32_t*)mask);
    const size_t mask_elts = (size_t)Bn * Sn * Sn;
    pack_mask_kernel<<<(unsigned)(mask_elts / 1024), 256>>>(mask);

    __half *ahi, *whi;
    cudaGetSymbolAddress((void**)&ahi, g_ahi);
    cudaGetSymbolAddress((void**)&whi, g_whi);

    // X (8 slices) + 4 weights -> fp16 in one launch
    cvt_all_kernel<<<dim3((unsigned)((size_t)Dn * Dn / 1024), 12), 256>>>(x, wq, wk, wv, wo);

    // QKV projections -> fp16 Q/K/V, single-pass
    dim3 g1(Dn / 128, Mtot / 128, 3);
    mma_gemm_kernel<<<g1, 256, DYNSM>>>(ahi, whi, nullptr, 0);

    // Dynamic-persistent flash attention -> writes g_ahi
    attn_mma_kernel<<<304, 256, ATT_SMEM>>>();

    // Output projection (single-pass)
    dim3 g3(Dn / 128, Mtot / 128, 1);
    mma_gemm_kernel<<<g3, 256, DYNSM>>>(ahi, whi + 3 * (size_t)Dn * Dn, out, 1);
}

// round 16
// speedup vs baseline: 1.1299x; 1.0681x over previous
#include <cuda_runtime.h>
#include <cuda_fp16.h>
#include <stdint.h>

#define Bn 4
#define Sn 2048
#define Dn 1024
#define Hn 16
#define HDn 64
#define Mtot (Bn * Sn)          // 8192
#define NITEMS (16 * 64)        // qt x (b*h) work items for attention

// Scratch (static device globals -- allocation-free per harness rules)
__device__ uint32_t g_maskbits[(size_t)Bn * Sn * Sn / 32];   // 1 bit / elt
__device__ int      g_mask_flag;
__device__ int      g_work;                                  // attention work counter

// fp16 operand buffers (all hi-only)
__device__ __half g_ahi[(size_t)Mtot * Dn];   // X hi, then attn-out hi
__device__ __half g_whi[(size_t)4 * Dn * Dn]; // wq,wk,wv,wo hi
__device__ __half g_qhi[(size_t)Bn * Hn * Sn * HDn];  // [B,H,S,HD]
__device__ __half g_khi[(size_t)Bn * Hn * Sn * HDn];
__device__ __half g_vhi[(size_t)Bn * Hn * Sn * HDn];

// ===========================================================================
// PTX helpers (base ISA: ldmatrix / mma.sync / cp.async)
// ===========================================================================
__device__ __forceinline__ uint32_t smem_u32(const void* p) {
    uint32_t a;
    asm("{ .reg .u64 t; cvta.to.shared.u64 t, %1; cvt.u32.u64 %0, t; }" : "=r"(a) : "l"(p));
    return a;
}

// hardware exp2 (MUFU.EX2) -- same unit __expf uses, minus the scale MUL
__device__ __forceinline__ float fex2(float x) {
    float r;
    asm("ex2.approx.ftz.f32 %0, %1;" : "=f"(r) : "f"(x));
    return r;
}

#define LDSM4(r0, r1, r2, r3, addr) \
    asm volatile("ldmatrix.sync.aligned.m8n8.x4.shared.b16 {%0,%1,%2,%3}, [%4];" \
        : "=r"(r0), "=r"(r1), "=r"(r2), "=r"(r3) : "r"(addr))

#define LDSM4T(r0, r1, r2, r3, addr) \
    asm volatile("ldmatrix.sync.aligned.m8n8.x4.trans.shared.b16 {%0,%1,%2,%3}, [%4];" \
        : "=r"(r0), "=r"(r1), "=r"(r2), "=r"(r3) : "r"(addr))

#define MMA16816(c, a0, a1, a2, a3, b0, b1) \
    asm volatile("mma.sync.aligned.m16n8k16.row.col.f32.f16.f16.f32 " \
        "{%0,%1,%2,%3}, {%4,%5,%6,%7}, {%8,%9}, {%0,%1,%2,%3};" \
        : "+f"((c)[0]), "+f"((c)[1]), "+f"((c)[2]), "+f"((c)[3]) \
        : "r"(a0), "r"(a1), "r"(a2), "r"(a3), "r"(b0), "r"(b1))

#define CPA16(dst, src) \
    asm volatile("cp.async.cg.shared.global [%0], [%1], 16;" :: "r"(dst), "l"(src) : "memory")
#define CPA_COMMIT() asm volatile("cp.async.commit_group;" ::: "memory")
#define CPA_WAITG(n) asm volatile("cp.async.wait_group %0;" :: "n"(n) : "memory")

// 0.125 * log2(e): QK^T scale folded into log2-domain softmax
#define SC2 0.18033688011112042f

// ===========================================================================
// Mask: dtype sniffer (also resets work counter) + vectorized bit-packer
// ===========================================================================
__global__ void detect_mask_kernel(const uint32_t* __restrict__ m)
{
    __shared__ int cnt_w;
    if (threadIdx.x == 0) { cnt_w = 0; g_work = 0; }
    __syncthreads();
    uint32_t w = m[threadIdx.x];
    if (w == 0u || w == 1u || w == 0x3F800000u) atomicAdd(&cnt_w, 1);
    __syncthreads();
    if (threadIdx.x == 0) g_mask_flag = (cnt_w > 200) ? 1 : 0;  // 1 = 4-byte elems
}

__global__ __launch_bounds__(256) void pack_mask_kernel(const void* __restrict__ m)
{
    const size_t idx = (size_t)blockIdx.x * 256 + threadIdx.x;
    const int lane = threadIdx.x & 31;
    uint32_t nib;
    if (g_mask_flag) {
        uint4 v = ((const uint4*)m)[idx];
        nib = (v.x != 0u) | ((v.y != 0u) << 1) | ((v.z != 0u) << 2) | ((v.w != 0u) << 3);
    } else {
        uint32_t v = ((const uint32_t*)m)[idx];
        nib = ((v & 0x000000FFu) ? 1u : 0u) | ((v & 0x0000FF00u) ? 2u : 0u)
            | ((v & 0x00FF0000u) ? 4u : 0u) | ((v & 0xFF000000u) ? 8u : 0u);
    }
    uint32_t sh = nib << (4 * (lane & 7));
    sh |= __shfl_xor_sync(0xffffffffu, sh, 1);
    sh |= __shfl_xor_sync(0xffffffffu, sh, 2);
    sh |= __shfl_xor_sync(0xffffffffu, sh, 4);
    if ((lane & 7) == 0) g_maskbits[idx >> 3] = sh;
}

// ===========================================================================
// fp32 -> fp16 hi conversion: one launch covers X (8 slices) + 4 weights.
// ===========================================================================
__global__ __launch_bounds__(256) void cvt_all_kernel(
    const float* __restrict__ x,
    const float* __restrict__ w0, const float* __restrict__ w1,
    const float* __restrict__ w2, const float* __restrict__ w3)
{
    const int z = blockIdx.y;
    const float* src;
    __half* dst;
    if (z < 8) {
        src = x   + (size_t)z * (Mtot / 8) * Dn;
        dst = g_ahi + (size_t)z * (Mtot / 8) * Dn;
    } else {
        const float* ws[4] = {w0, w1, w2, w3};
        src = ws[z - 8];
        dst = g_whi + (size_t)(z - 8) * Dn * Dn;
    }
    const size_t i = (size_t)blockIdx.x * 256 + threadIdx.x;
    float4 v = ((const float4*)src)[i];
    __half2 a = __floats2half2_rn(v.x, v.y);
    __half2 b = __floats2half2_rn(v.z, v.w);
    ((uint2*)dst)[i] = make_uint2(*(uint32_t*)&a, *(uint32_t*)&b);
}

// ===========================================================================
// fp16 tensor-core GEMM (R12-proven config): C[128x128] = Ah @ Wh^T
// KC=32, 4-stage cp.async ring, ONE __syncthreads per K-chunk.
// ===========================================================================
#define KC 32
#define PITCH 40                 // halves per smem row (80 B)
#define TILE_B (128 * PITCH * 2) // 10240
#define STG (2 * TILE_B)         // Ah, Bh = 20480
#define NSTAGE 4
#define DYNSM (NSTAGE * STG)     // 81920

__global__ __launch_bounds__(256, 2) void mma_gemm_kernel(
    const __half* __restrict__ Ahi,
    const __half* __restrict__ Whi,
    float* __restrict__ out,
    int mode)
{
    extern __shared__ char dsm[];
    const uint32_t sbase = smem_u32(dsm);

    const int tid  = threadIdx.x;
    const int lane = tid & 31;
    const int wid  = tid >> 5;
    const int wr   = wid >> 2;
    const int wc   = wid & 3;
    const int bm   = blockIdx.y * 128;
    const int bn   = blockIdx.x * 128;
    const int z    = blockIdx.z;

    const __half* WhiZ = Whi + (size_t)z * Dn * Dn;

    const int row = tid >> 1;
    const int gh  = tid & 1;
    const __half* sA_h = Ahi  + (size_t)(bm + row) * Dn + gh * 16;
    const __half* sB_h = WhiZ + (size_t)(bn + row) * Dn + gh * 16;
    const uint32_t sd0 = sbase + (uint32_t)row * (PITCH * 2) + gh * 32;

    const int NC = Dn / KC;     // 32
    auto issue = [&](int ck) {
        const uint32_t sd = sd0 + (ck & (NSTAGE - 1)) * STG;
        const size_t o = (size_t)ck * KC;
        CPA16(sd,                 sA_h + o);
        CPA16(sd + 16,            sA_h + o + 8);
        CPA16(sd + TILE_B,        sB_h + o);
        CPA16(sd + TILE_B + 16,   sB_h + o + 8);
        CPA_COMMIT();
    };

    float acc[4][4][4];
    #pragma unroll
    for (int i = 0; i < 4; i++)
        #pragma unroll
        for (int j = 0; j < 4; j++)
            #pragma unroll
            for (int v = 0; v < 4; v++) acc[i][j][v] = 0.f;

    issue(0);
    issue(1);
    issue(2);

    for (int ck = 0; ck < NC; ck++) {
        if (ck <= NC - 3)      { CPA_WAITG(2); }
        else if (ck == NC - 2) { CPA_WAITG(1); }
        else                   { CPA_WAITG(0); }
        __syncthreads();
        if (ck + 3 < NC) issue(ck + 3);

        const uint32_t stg = sbase + (ck & (NSTAGE - 1)) * STG;
        #pragma unroll
        for (int ks = 0; ks < 2; ks++) {
            uint32_t b[4][2];
            #pragma unroll
            for (int jj = 0; jj < 2; jj++) {
                int n = wc * 32 + jj * 16 + ((lane >> 4) & 1) * 8 + (lane & 7);
                int k = ks * 16 + ((lane >> 3) & 1) * 8;
                uint32_t ad = stg + TILE_B + (uint32_t)(n * PITCH + k) * 2;
                LDSM4(b[2 * jj][0], b[2 * jj][1], b[2 * jj + 1][0], b[2 * jj + 1][1], ad);
            }
            #pragma unroll
            for (int i = 0; i < 4; i++) {
                int m = wr * 64 + i * 16 + ((lane >> 3) & 1) * 8 + (lane & 7);
                int k = ks * 16 + ((lane >> 4) & 1) * 8;
                uint32_t adh = stg + (uint32_t)(m * PITCH + k) * 2;
                uint32_t a0, a1, a2, a3;
                LDSM4(a0, a1, a2, a3, adh);
                #pragma unroll
                for (int j = 0; j < 4; j++)
                    MMA16816(acc[i][j], a0, a1, a2, a3, b[j][0], b[j][1]);
            }
        }
    }

    // ---- epilogue ----
    #pragma unroll
    for (int i = 0; i < 4; i++) {
        #pragma unroll
        for (int j = 0; j < 4; j++) {
            int ml = wr * 64 + i * 16 + (lane >> 2);
            int nl = wc * 32 + j * 8 + 2 * (lane & 3);
            int m = bm + ml, n = bn + nl;
            if (mode == 0) {
                __half* dh = (z == 0) ? g_qhi : (z == 1) ? g_khi : g_vhi;
                int bb2 = m >> 11, ss = m & 2047;
                int hh = n >> 6,  hd = n & 63;
                size_t base = (((size_t)bb2 * Hn + hh) * Sn + ss) * HDn + hd;
                __half2 h = __floats2half2_rn(acc[i][j][0], acc[i][j][1]);
                *(uint32_t*)&dh[base] = *(uint32_t*)&h;
                h = __floats2half2_rn(acc[i][j][2], acc[i][j][3]);
                *(uint32_t*)&dh[base + 8 * HDn] = *(uint32_t*)&h;
            } else {
                *(float2*)&out[(size_t)m * Dn + n] =
                    make_float2(acc[i][j][0], acc[i][j][1]);
                *(float2*)&out[(size_t)(m + 8) * Dn + n] =
                    make_float2(acc[i][j][2], acc[i][j][3]);
            }
        }
    }
}

// ===========================================================================
// Tensor-core flash attention, dynamic-persistent CTAs.
// log2-domain online softmax, tree reductions, upfront P pack.
// ===========================================================================
#define AP     72                 // halves per row (144 B)
#define APB    144
#define TILE18 18432              // 128 * 144
#define OFF_KH 0
#define OFF_VH 18432
#define OFF_MK 36864              // 128 rows x 16 B of bits
#define KVBUF  38912              // 2*18432 + 2048
#define QSZ    18432
#define ATT_SMEM (QSZ + 2 * KVBUF)   // 96256

__global__ __launch_bounds__(256, 2) void attn_mma_kernel()
{
    extern __shared__ char smn[];
    const uint32_t sb = smem_u32(smn);
    __shared__ int s_item;
    const int tid = threadIdx.x, lane = tid & 31, w = tid >> 5;
    const int row = tid >> 1, seg = tid & 1;
    const uint32_t rowb = (uint32_t)row * APB + seg * 64;

    const int wq0  = w * 16;
    const int r_lo = lane >> 2, c4 = lane & 3;
    const int mA = wq0 + ((lane >> 3) & 1) * 8 + (lane & 7);
    const int kA = ((lane >> 4) & 1) * 8;
    const uint32_t aQh = sb + (uint32_t)(mA * AP + kA) * 2;
    const int nK = ((lane >> 4) & 1) * 8 + (lane & 7);
    const int kK = ((lane >> 3) & 1) * 8;
    const int kV = ((lane >> 3) & 1) * 8 + (lane & 7);
    const int nV = ((lane >> 4) & 1) * 8;

    for (;;) {
        __syncthreads();                     // drain prior item's smem use
        if (tid == 0) s_item = atomicAdd(&g_work, 1);
        __syncthreads();
        const int item = s_item;
        if (item >= NITEMS) break;

        const int bh = item >> 4;            // consecutive grabs share head -> L2
        const int qt = item & 15;
        const int b = bh >> 4, h = bh & 15;
        const int qbase = qt * 128;
        const size_t head = (size_t)bh * Sn * HDn;

        // Q tile load (plain global reads)
        {
            const uint4* qh = (const uint4*)(g_qhi + head + (size_t)(qbase + row) * HDn + seg * 32);
            uint4* dh = (uint4*)(smn + rowb);
            #pragma unroll
            for (int i = 0; i < 4; i++) dh[i] = qh[i];
        }

        const char* mbits_row = (const char*)g_maskbits + ((size_t)b * Sn + qbase + row) * (Sn / 8);
        const char* gkh = (const char*)(g_khi + head + (size_t)row * HDn + seg * 32);
        const char* gvh = (const char*)(g_vhi + head + (size_t)row * HDn + seg * 32);

        auto issue_tile = [&](int kt, int s) {
            const uint32_t bb = sb + QSZ + s * KVBUF;
            const size_t go = (size_t)kt * 128 * HDn * 2;
            #pragma unroll
            for (int i = 0; i < 4; i++) {
                CPA16(bb + OFF_KH + rowb + i * 16, gkh + go + i * 16);
                CPA16(bb + OFF_VH + rowb + i * 16, gvh + go + i * 16);
            }
            if (seg == 0)
                CPA16(bb + OFF_MK + (uint32_t)row * 16, mbits_row + kt * 16);
            CPA_COMMIT();
        };

        float o[8][4];
        #pragma unroll
        for (int j = 0; j < 8; j++)
            #pragma unroll
            for (int v = 0; v < 4; v++) o[j][v] = 0.f;
        float m_r0 = -1e30f, m_r1 = -1e30f, l_r0 = 0.f, l_r1 = 0.f;  // log2 domain

        issue_tile(0, 0);

        for (int kt = 0; kt < 16; kt++) {
            const int s = kt & 1;
            CPA_WAITG(0);
            __syncthreads();
            if (kt < 15) issue_tile(kt + 1, s ^ 1);
            const uint32_t bb = sb + QSZ + s * KVBUF;

            // ---- S = Qh Kh^T ----
            float sacc[16][4];
            #pragma unroll
            for (int j = 0; j < 16; j++)
                #pragma unroll
                for (int v = 0; v < 4; v++) sacc[j][v] = 0.f;

            #pragma unroll
            for (int ks = 0; ks < 4; ks++) {
                uint32_t ah0, ah1, ah2, ah3;
                LDSM4(ah0, ah1, ah2, ah3, aQh + ks * 32);
                #pragma unroll
                for (int jj = 0; jj < 8; jj++) {
                    const int j0 = 2 * jj;
                    const uint32_t kaddr =
                        bb + OFF_KH + (uint32_t)((j0 * 8 + nK) * AP + ks * 16 + kK) * 2;
                    uint32_t b0, b1, b2, b3;
                    LDSM4(b0, b1, b2, b3, kaddr);
                    MMA16816(sacc[j0],     ah0, ah1, ah2, ah3, b0, b1);
                    MMA16816(sacc[j0 + 1], ah0, ah1, ah2, ah3, b2, b3);
                }
            }

            // ---- bit-mask + online softmax (log2 domain, tree reductions) ----
            const uint4 mw0 = *(const uint4*)(smn + QSZ + s * KVBUF + OFF_MK + (wq0 + r_lo) * 16);
            const uint4 mw1 = *(const uint4*)(smn + QSZ + s * KVBUF + OFF_MK + (wq0 + r_lo + 8) * 16);
            uint32_t w0a[4] = {mw0.x, mw0.y, mw0.z, mw0.w};
            uint32_t w1a[4] = {mw1.x, mw1.y, mw1.z, mw1.w};
            float tA0[4] = {-1e30f, -1e30f, -1e30f, -1e30f};
            float tA1[4] = {-1e30f, -1e30f, -1e30f, -1e30f};
            #pragma unroll
            for (int j = 0; j < 16; j++) {
                const uint32_t bits0 = w0a[j >> 2] >> (8 * (j & 3) + 2 * c4);
                const uint32_t bits1 = w1a[j >> 2] >> (8 * (j & 3) + 2 * c4);
                float s0 = (bits0 & 1u) ? sacc[j][0] * SC2 : -1e30f;
                float s1 = (bits0 & 2u) ? sacc[j][1] * SC2 : -1e30f;
                float s2 = (bits1 & 1u) ? sacc[j][2] * SC2 : -1e30f;
                float s3 = (bits1 & 2u) ? sacc[j][3] * SC2 : -1e30f;
                sacc[j][0] = s0; sacc[j][1] = s1; sacc[j][2] = s2; sacc[j][3] = s3;
                tA0[j & 3] = fmaxf(tA0[j & 3], fmaxf(s0, s1));
                tA1[j & 3] = fmaxf(tA1[j & 3], fmaxf(s2, s3));
            }
            float tm0 = fmaxf(fmaxf(tA0[0], tA0[1]), fmaxf(tA0[2], tA0[3]));
            float tm1 = fmaxf(fmaxf(tA1[0], tA1[1]), fmaxf(tA1[2], tA1[3]));
            tm0 = fmaxf(tm0, __shfl_xor_sync(0xffffffffu, tm0, 1));
            tm0 = fmaxf(tm0, __shfl_xor_sync(0xffffffffu, tm0, 2));
            tm1 = fmaxf(tm1, __shfl_xor_sync(0xffffffffu, tm1, 1));
            tm1 = fmaxf(tm1, __shfl_xor_sync(0xffffffffu, tm1, 2));
            const float mn0 = fmaxf(m_r0, tm0), mn1 = fmaxf(m_r1, tm1);
            const float al_0 = fex2(m_r0 - mn0), al_1 = fex2(m_r1 - mn1);
            m_r0 = mn0; m_r1 = mn1;

            float pA0[4] = {0.f, 0.f, 0.f, 0.f};
            float pA1[4] = {0.f, 0.f, 0.f, 0.f};
            #pragma unroll
            for (int j = 0; j < 16; j++) {
                float p0 = fex2(sacc[j][0] - mn0); sacc[j][0] = p0;
                float p1 = fex2(sacc[j][1] - mn0); sacc[j][1] = p1;
                float p2 = fex2(sacc[j][2] - mn1); sacc[j][2] = p2;
                float p3 = fex2(sacc[j][3] - mn1); sacc[j][3] = p3;
                pA0[j & 3] += p0 + p1;
                pA1[j & 3] += p2 + p3;
            }
            float ps0 = (pA0[0] + pA0[1]) + (pA0[2] + pA0[3]);
            float ps1 = (pA1[0] + pA1[1]) + (pA1[2] + pA1[3]);
            ps0 += __shfl_xor_sync(0xffffffffu, ps0, 1);
            ps0 += __shfl_xor_sync(0xffffffffu, ps0, 2);
            ps1 += __shfl_xor_sync(0xffffffffu, ps1, 1);
            ps1 += __shfl_xor_sync(0xffffffffu, ps1, 2);
            l_r0 = l_r0 * al_0 + ps0;
            l_r1 = l_r1 * al_1 + ps1;

            // upfront P pack (frees sacc before PV)
            uint32_t pp[8][4];
            #pragma unroll
            for (int kt2 = 0; kt2 < 8; kt2++) {
                const int j0 = 2 * kt2;
                __half2 hp;
                hp = __floats2half2_rn(sacc[j0][0], sacc[j0][1]);     pp[kt2][0] = *(uint32_t*)&hp;
                hp = __floats2half2_rn(sacc[j0][2], sacc[j0][3]);     pp[kt2][1] = *(uint32_t*)&hp;
                hp = __floats2half2_rn(sacc[j0 + 1][0], sacc[j0 + 1][1]); pp[kt2][2] = *(uint32_t*)&hp;
                hp = __floats2half2_rn(sacc[j0 + 1][2], sacc[j0 + 1][3]); pp[kt2][3] = *(uint32_t*)&hp;
            }
            #pragma unroll
            for (int j = 0; j < 8; j++) {
                o[j][0] *= al_0; o[j][1] *= al_0; o[j][2] *= al_1; o[j][3] *= al_1;
            }

            // ---- O += Ph Vh (V via ldmatrix.trans) ----
            #pragma unroll
            for (int kt2 = 0; kt2 < 8; kt2++) {
                #pragma unroll
                for (int jj = 0; jj < 4; jj++) {
                    const int jv = 2 * jj;
                    const uint32_t va =
                        bb + OFF_VH + (uint32_t)((kt2 * 16 + kV) * AP + jv * 8 + nV) * 2;
                    uint32_t v0, v1, v2, v3;
                    LDSM4T(v0, v1, v2, v3, va);
                    MMA16816(o[jv],     pp[kt2][0], pp[kt2][1], pp[kt2][2], pp[kt2][3], v0, v1);
                    MMA16816(o[jv + 1], pp[kt2][0], pp[kt2][1], pp[kt2][2], pp[kt2][3], v2, v3);
                }
            }
        }

        // ---- epilogue: O/l -> fp16 into out-GEMM operand buffer ----
        const float inv0 = 1.f / fmaxf(l_r0, 1e-30f);
        const float inv1 = 1.f / fmaxf(l_r1, 1e-30f);
        const int r1g = qbase + wq0 + r_lo;
        #pragma unroll
        for (int j = 0; j < 8; j++) {
            const size_t idx0 = ((size_t)b * Sn + r1g) * Dn + h * 64 + j * 8 + 2 * c4;
            __half2 h2;
            h2 = __floats2half2_rn(o[j][0] * inv0, o[j][1] * inv0);
            *(uint32_t*)&g_ahi[idx0] = *(uint32_t*)&h2;
            h2 = __floats2half2_rn(o[j][2] * inv1, o[j][3] * inv1);
            *(uint32_t*)&g_ahi[idx0 + 8 * Dn] = *(uint32_t*)&h2;
        }
    }
}

// ---------------------------------------------------------------------------
extern "C" void kernel_launch(void* const* d_in, const int* in_sizes, int n_in,
                              void* d_out, int out_size)
{
    const float* x    = (const float*)d_in[0];
    const void*  mask = d_in[1];
    const float* wq   = (const float*)d_in[2];
    const float* wk   = (const float*)d_in[3];
    const float* wv   = (const float*)d_in[4];
    const float* wo   = (const float*)d_in[5];
    float* out = (float*)d_out;

    cudaFuncSetAttribute(mma_gemm_kernel,
                         cudaFuncAttributeMaxDynamicSharedMemorySize, DYNSM);
    cudaFuncSetAttribute(attn_mma_kernel,
                         cudaFuncAttributeMaxDynamicSharedMemorySize, ATT_SMEM);

    detect_mask_kernel<<<1, 256>>>((const uint32_t*)mask);
    const size_t mask_elts = (size_t)Bn * Sn * Sn;
    pack_mask_kernel<<<(unsigned)(mask_elts / 1024), 256>>>(mask);

    __half *ahi, *whi;
    cudaGetSymbolAddress((void**)&ahi, g_ahi);
    cudaGetSymbolAddress((void**)&whi, g_whi);

    // X (8 slices) + 4 weights -> fp16 in one launch
    cvt_all_kernel<<<dim3((unsigned)((size_t)Dn * Dn / 1024), 12), 256>>>(x, wq, wk, wv, wo);

    // QKV projections -> fp16 Q/K/V, single-pass
    dim3 g1(Dn / 128, Mtot / 128, 3);
    mma_gemm_kernel<<<g1, 256, DYNSM>>>(ahi, whi, nullptr, 0);

    // Dynamic-persistent flash attention -> writes g_ahi
    attn_mma_kernel<<<304, 256, ATT_SMEM>>>();

    // Output projection (single-pass)
    dim3 g3(Dn / 128, Mtot / 128, 1);
    mma_gemm_kernel<<<g3, 256, DYNSM>>>(ahi, whi + 3 * (size_t)Dn * Dn, out, 1);
}